// round 1
// baseline (speedup 1.0000x reference)
#include <cuda_runtime.h>

#define EPSV 1e-10f
#define BB 32
#define TT 512
#define NN 128

// Scratch (static device globals; no allocation).
__device__ float g_trans[NN * NN];   // trans_norm[m][n] at [m*NN+n]
__device__ float g_transT[NN * NN];  // trans_norm[m][n] at [n*NN+m]
__device__ float g_logprior[NN];
__device__ float g_L[BB * TT * NN];  // forward trellis (8 MB)

// ---------------- prep: normalize transition rows + prior ----------------
__global__ void prep_kernel(const float* __restrict__ trans,
                            const float* __restrict__ prior) {
    const int tid = threadIdx.x;  // 0..127
    __shared__ float sred[4];

    // prior: clamp, normalize, log
    float pv = fmaxf(prior[tid], EPSV);
    float s = pv;
    #pragma unroll
    for (int o = 16; o > 0; o >>= 1) s += __shfl_xor_sync(0xffffffffu, s, o);
    if ((tid & 31) == 0) sred[tid >> 5] = s;
    __syncthreads();
    float Z = sred[0] + sred[1] + sred[2] + sred[3];
    g_logprior[tid] = __logf(pv / Z);

    // transition row tid: clamp + row-normalize; write both layouts
    float rs = 0.f;
    for (int n = 0; n < NN; n++) rs += fmaxf(trans[tid * NN + n], EPSV);
    for (int n = 0; n < NN; n++) {
        float v = fmaxf(trans[tid * NN + n], EPSV) / rs;
        g_trans[tid * NN + n] = v;
        g_transT[n * NN + tid] = v;
    }
}

// ---------------- forward: L[t] = em[t] + logsumexp-step ----------------
__global__ void __launch_bounds__(NN, 1)
forward_kernel(const float* __restrict__ em) {
    const int n = threadIdx.x;
    const int b = blockIdx.x;
    __shared__ float sh_e[NN];
    __shared__ float sred[4];

    // register-cache column n of trans_norm (coalesced)
    float C[NN];
    #pragma unroll
    for (int m = 0; m < NN; m++) C[m] = g_trans[m * NN + n];

    const float* emb = em + (size_t)b * TT * NN;
    float* Lb = g_L + (size_t)b * TT * NN;

    float L = g_logprior[n] + emb[n];
    Lb[n] = L;

    float em_t = emb[NN + n];  // em for t=1
    for (int t = 1; t < TT; t++) {
        float em_next = (t + 1 < TT) ? emb[(t + 1) * NN + n] : 0.f;  // prefetch

        // block max of L
        float wm = L;
        #pragma unroll
        for (int o = 16; o > 0; o >>= 1)
            wm = fmaxf(wm, __shfl_xor_sync(0xffffffffu, wm, o));
        if ((n & 31) == 0) sred[n >> 5] = wm;
        __syncthreads();  // S1 (also fences previous iter's sh_e reads)
        float A = fmaxf(fmaxf(sred[0], sred[1]), fmaxf(sred[2], sred[3]));

        sh_e[n] = __expf(L - A);
        __syncthreads();  // S2

        const float4* e4 = (const float4*)sh_e;
        float a0 = 0.f, a1 = 0.f, a2 = 0.f, a3 = 0.f;
        #pragma unroll
        for (int k = 0; k < NN / 4; k++) {
            float4 ev = e4[k];
            a0 = fmaf(ev.x, C[4 * k + 0], a0);
            a1 = fmaf(ev.y, C[4 * k + 1], a1);
            a2 = fmaf(ev.z, C[4 * k + 2], a2);
            a3 = fmaf(ev.w, C[4 * k + 3], a3);
        }
        float v = (a0 + a1) + (a2 + a3);

        L = em_t + A + __logf(v);
        Lb[t * NN + n] = L;
        em_t = em_next;
    }
}

// ---------------- backward: soft-path propagation ----------------
__global__ void __launch_bounds__(NN, 1)
backward_kernel(const float* __restrict__ em, float* __restrict__ out) {
    const int n = threadIdx.x;
    const int b = blockIdx.x;
    __shared__ float sh_w[NN];
    __shared__ float sredA[4], sredB[4], sredC[4];

    // register-cache row n of trans_norm (coalesced via transposed layout)
    float R[NN];
    #pragma unroll
    for (int k = 0; k < NN; k++) R[k] = g_transT[k * NN + n];

    const float* emb = em + (size_t)b * TT * NN;
    const float* Lb = g_L + (size_t)b * TT * NN;
    float* outb = out + (size_t)b * TT * NN;

    // t = T-1: p = softmax(L[T-1])
    float Lnext = Lb[(TT - 1) * NN + n];
    float p;
    {
        float wm = Lnext;
        #pragma unroll
        for (int o = 16; o > 0; o >>= 1)
            wm = fmaxf(wm, __shfl_xor_sync(0xffffffffu, wm, o));
        if ((n & 31) == 0) sredA[n >> 5] = wm;
        __syncthreads();
        float A = fmaxf(fmaxf(sredA[0], sredA[1]), fmaxf(sredA[2], sredA[3]));
        float ex = __expf(Lnext - A);
        float ss = ex;
        #pragma unroll
        for (int o = 16; o > 0; o >>= 1) ss += __shfl_xor_sync(0xffffffffu, ss, o);
        if ((n & 31) == 0) sredC[n >> 5] = ss;
        __syncthreads();
        float Z = sredC[0] + sredC[1] + sredC[2] + sredC[3];
        p = ex / Z;
        outb[(TT - 1) * NN + n] = p;
        __syncthreads();  // isolate init reductions from loop's first writes
    }

    float em_next = emb[(TT - 1) * NN + n];   // em at t+1 for t=T-2
    float Lt_pref = Lb[(TT - 2) * NN + n];    // L[t] for t=T-2

    for (int t = TT - 2; t >= 0; t--) {
        float Lt = Lt_pref;
        float em_t1 = em_next;
        if (t > 0) {  // prefetch next iteration's globals
            Lt_pref = Lb[(t - 1) * NN + n];
            em_next = emb[t * NN + n];
        }

        float sm = Lnext - em_t1;  // logsumexp value at step t (state n)
        float g = (p > 0.f) ? (__logf(p) - sm) : -3.0e38f;

        // joint block max of g and Lt
        float wg = g, wl = Lt;
        #pragma unroll
        for (int o = 16; o > 0; o >>= 1) {
            wg = fmaxf(wg, __shfl_xor_sync(0xffffffffu, wg, o));
            wl = fmaxf(wl, __shfl_xor_sync(0xffffffffu, wl, o));
        }
        if ((n & 31) == 0) { sredA[n >> 5] = wg; sredB[n >> 5] = wl; }
        __syncthreads();  // S1 (also fences previous iter's sh_w reads)
        float shift = fmaxf(fmaxf(sredA[0], sredA[1]), fmaxf(sredA[2], sredA[3]));
        float A2 = fmaxf(fmaxf(sredB[0], sredB[1]), fmaxf(sredB[2], sredB[3]));

        sh_w[n] = (p > 0.f) ? __expf(g - shift) : 0.f;
        __syncthreads();  // S2

        const float4* w4 = (const float4*)sh_w;
        float a0 = 0.f, a1 = 0.f, a2 = 0.f, a3 = 0.f;
        #pragma unroll
        for (int k = 0; k < NN / 4; k++) {
            float4 wv = w4[k];
            a0 = fmaf(wv.x, R[4 * k + 0], a0);
            a1 = fmaf(wv.y, R[4 * k + 1], a1);
            a2 = fmaf(wv.z, R[4 * k + 2], a2);
            a3 = fmaf(wv.w, R[4 * k + 3], a3);
        }
        float acc = (a0 + a1) + (a2 + a3);
        float u = __expf(Lt - A2) * acc;

        // block sum of u (renormalize; true p sums to 1)
        float su = u;
        #pragma unroll
        for (int o = 16; o > 0; o >>= 1) su += __shfl_xor_sync(0xffffffffu, su, o);
        if ((n & 31) == 0) sredC[n >> 5] = su;
        __syncthreads();  // S3
        float Z = sredC[0] + sredC[1] + sredC[2] + sredC[3];

        p = u / Z;
        outb[t * NN + n] = p;
        Lnext = Lt;
    }
}

extern "C" void kernel_launch(void* const* d_in, const int* in_sizes, int n_in,
                              void* d_out, int out_size) {
    const float* trans = (const float*)d_in[0];  // (128,128)
    const float* em    = (const float*)d_in[1];  // (32,512,128)
    const float* prior = (const float*)d_in[2];  // (128,)
    float* out = (float*)d_out;                  // (32,512,128)

    prep_kernel<<<1, NN>>>(trans, prior);
    forward_kernel<<<BB, NN>>>(em);
    backward_kernel<<<BB, NN>>>(em, out);
}

// round 2
// speedup vs baseline: 1.8656x; 1.8656x over previous
#include <cuda_runtime.h>

#define EPSV 1e-10f
#define BB 32
#define TT 512
#define NN 128

// Scratch (static device globals; no allocation).
__device__ float g_trans[NN * NN];   // trans_norm[prev][next]
__device__ float g_transT[NN * NN];  // [k][m] = trans_norm[m][k]
__device__ float g_prior[NN];        // normalized prior (linear)
__device__ float g_W[BB * TT * NN];  // linear trellis w_t  (scale pinned per step)
__device__ float g_V[BB * TT * NN];  // v_t = w_t * exp(-em_t) (same scale family)

// ---------- packed f32x2 helpers ----------
__device__ __forceinline__ unsigned long long fma2(unsigned long long a,
                                                   unsigned long long b,
                                                   unsigned long long c) {
    unsigned long long d;
    asm("fma.rn.f32x2 %0, %1, %2, %3;" : "=l"(d) : "l"(a), "l"(b), "l"(c));
    return d;
}
__device__ __forceinline__ float2 unpack2(unsigned long long v) {
    float2 r;
    asm("mov.b64 {%0, %1}, %2;" : "=f"(r.x), "=f"(r.y) : "l"(v));
    return r;
}
__device__ __forceinline__ unsigned long long pack2(float lo, float hi) {
    unsigned long long v;
    asm("mov.b64 %0, {%1, %2};" : "=l"(v) : "f"(lo), "f"(hi));
    return v;
}

__device__ __forceinline__ float blk_sum128(float v, float* sred) {
    #pragma unroll
    for (int o = 16; o > 0; o >>= 1) v += __shfl_xor_sync(0xffffffffu, v, o);
    if ((threadIdx.x & 31) == 0) sred[threadIdx.x >> 5] = v;
    __syncthreads();
    return (sred[0] + sred[1]) + (sred[2] + sred[3]);
}

// ---------------- prep: normalize transition rows + prior (parallel) ----------------
__global__ void prep_kernel(const float* __restrict__ trans,
                            const float* __restrict__ prior) {
    const int r = blockIdx.x;   // row (prev state)
    const int n = threadIdx.x;  // col (next state)
    __shared__ float sred[4];

    float v = fmaxf(trans[r * NN + n], EPSV);
    float rs = blk_sum128(v, sred);
    float tn = v / rs;
    g_trans[r * NN + n] = tn;
    g_transT[n * NN + r] = tn;

    if (r == 0) {
        float pv = fmaxf(prior[n], EPSV);
        __syncthreads();  // protect sred reuse
        float ps = blk_sum128(pv, sred);
        g_prior[n] = pv / ps;
    }
}

// ---------------- forward: linear-domain trellis ----------------
__global__ void __launch_bounds__(NN, 1)
forward_kernel(const float* __restrict__ em) {
    const int n = threadIdx.x;
    const int b = blockIdx.x;
    __shared__ ulonglong2 sh[2][NN / 4];

    // register-cache column n of trans_norm, packed in f32x2 pairs over prev
    unsigned long long C2[NN / 2];
    #pragma unroll
    for (int k = 0; k < NN / 2; k++)
        C2[k] = pack2(g_trans[(2 * k) * NN + n], g_trans[(2 * k + 1) * NN + n]);

    const float* emb = em + (size_t)b * TT * NN;
    float* Wb = g_W + (size_t)b * TT * NN;
    float* Vb = g_V + (size_t)b * TT * NN;

    float w = g_prior[n] * __expf(emb[n]);
    Wb[n] = w;

    float em_t = emb[NN + n];  // em for t=1
    for (int t = 1; t < TT; t++) {
        const int buf = t & 1;
        float* shf = (float*)sh[buf];
        shf[n] = w;
        __syncthreads();  // ONE barrier per step (double-buffered)

        float em_next = (t + 1 < TT) ? emb[(t + 1) * NN + n] : 0.f;  // prefetch
        float s0 = shf[0];  // broadcast scale pin

        const ulonglong2* sp = sh[buf];
        unsigned long long a0 = 0ull, a1 = 0ull, a2 = 0ull, a3 = 0ull;
        #pragma unroll
        for (int k = 0; k < NN / 4; k += 2) {
            ulonglong2 u0 = sp[k];
            ulonglong2 u1 = sp[k + 1];
            a0 = fma2(u0.x, C2[2 * k + 0], a0);
            a1 = fma2(u0.y, C2[2 * k + 1], a1);
            a2 = fma2(u1.x, C2[2 * k + 2], a2);
            a3 = fma2(u1.y, C2[2 * k + 3], a3);
        }
        float2 f0 = unpack2(a0), f1 = unpack2(a1), f2 = unpack2(a2), f3 = unpack2(a3);
        float v = ((f0.x + f0.y) + (f1.x + f1.y)) + ((f2.x + f2.y) + (f3.x + f3.y));

        float pin = (s0 > 1e-30f) ? s0 : 1.0f;
        float vh = v * __fdividef(1.0f, pin);

        Vb[t * NN + n] = vh;
        w = __expf(em_t) * vh;
        Wb[t * NN + n] = w;
        em_t = em_next;
    }
}

// ---------------- backward: linear soft-path (no exp/log at all) ----------------
__global__ void __launch_bounds__(NN, 1)
backward_kernel(float* __restrict__ out) {
    const int n = threadIdx.x;
    const int b = blockIdx.x;
    __shared__ ulonglong2 sh[2][NN / 4];

    // register-cache row n of trans_norm (coalesced via transposed layout), packed
    unsigned long long R2[NN / 2];
    #pragma unroll
    for (int k = 0; k < NN / 2; k++)
        R2[k] = pack2(g_transT[(2 * k) * NN + n], g_transT[(2 * k + 1) * NN + n]);

    const float* Wb = g_W + (size_t)b * TT * NN;
    const float* Vb = g_V + (size_t)b * TT * NN;
    float* outb = out + (size_t)b * TT * NN;

    // t = T-1: unnormalized p = w_{T-1} (softmax denominator deferred to norm_kernel)
    float p = Wb[(TT - 1) * NN + n];
    outb[(TT - 1) * NN + n] = p;

    float v_next = Vb[(TT - 1) * NN + n];  // v_{t+1} for t=T-2
    float w_t = Wb[(TT - 2) * NN + n];     // w_t for t=T-2

    for (int t = TT - 2; t >= 0; t--) {
        const int buf = t & 1;
        float* shf = (float*)sh[buf];
        float q = __fdividef(p, v_next);
        shf[n] = q;
        __syncthreads();  // ONE barrier per step

        // prefetch next iteration's trellis values
        float v_pref = (t > 0) ? Vb[t * NN + n] : 0.f;
        float w_pref = (t > 0) ? Wb[(t - 1) * NN + n] : 0.f;
        float q0 = shf[0];

        const ulonglong2* sp = sh[buf];
        unsigned long long a0 = 0ull, a1 = 0ull, a2 = 0ull, a3 = 0ull;
        #pragma unroll
        for (int k = 0; k < NN / 4; k += 2) {
            ulonglong2 u0 = sp[k];
            ulonglong2 u1 = sp[k + 1];
            a0 = fma2(u0.x, R2[2 * k + 0], a0);
            a1 = fma2(u0.y, R2[2 * k + 1], a1);
            a2 = fma2(u1.x, R2[2 * k + 2], a2);
            a3 = fma2(u1.y, R2[2 * k + 3], a3);
        }
        float2 f0 = unpack2(a0), f1 = unpack2(a1), f2 = unpack2(a2), f3 = unpack2(a3);
        float acc = ((f0.x + f0.y) + (f1.x + f1.y)) + ((f2.x + f2.y) + (f3.x + f3.y));

        float pin = (q0 > 1e-30f) ? q0 : 1.0f;
        p = w_t * acc * __fdividef(1.0f, pin);

        outb[t * NN + n] = p;
        v_next = v_pref;
        w_t = w_pref;
    }
}

// ---------------- final row normalization (full-chip parallel) ----------------
__global__ void norm_kernel(float* __restrict__ out) {
    const int wid = threadIdx.x >> 5;
    const int lane = threadIdx.x & 31;
    const size_t row = (size_t)blockIdx.x * 4 + wid;  // row over B*T
    float4* p = (float4*)(out + row * NN);
    float4 v = p[lane];
    float s = (v.x + v.y) + (v.z + v.w);
    #pragma unroll
    for (int o = 16; o > 0; o >>= 1) s += __shfl_xor_sync(0xffffffffu, s, o);
    float inv = __fdividef(1.0f, s);
    v.x *= inv; v.y *= inv; v.z *= inv; v.w *= inv;
    p[lane] = v;
}

extern "C" void kernel_launch(void* const* d_in, const int* in_sizes, int n_in,
                              void* d_out, int out_size) {
    const float* trans = (const float*)d_in[0];  // (128,128)
    const float* em    = (const float*)d_in[1];  // (32,512,128)
    const float* prior = (const float*)d_in[2];  // (128,)
    float* out = (float*)d_out;                  // (32,512,128)

    prep_kernel<<<NN, NN>>>(trans, prior);
    forward_kernel<<<BB, NN>>>(em);
    backward_kernel<<<BB, NN>>>(out);
    norm_kernel<<<BB * TT / 4, NN>>>(out);
}